// round 6
// baseline (speedup 1.0000x reference)
#include <cuda_runtime.h>
#include <cstdint>

// Centroids: out[n] = argmin_c || latent[n] - coords[c] ||^2
//          = argmin_c ( |c|^2 - 2 * latent[n].coords[c] )   (|x|^2 drops out)
//
// Same proven-simple kernel as R5; ONLY change: output indices written as
// FLOAT32 (converted-dataset output dtype). Indices 0..2047 are exact in fp32.

#define THREADS 256
#define TILE_C  32
#define DIM     128

__global__ void __launch_bounds__(THREADS, 1)
centroids_argmin_kernel(const float* __restrict__ latent,
                        const float* __restrict__ coords,
                        float* __restrict__ out,
                        int n_rows, int n_cent)
{
    __shared__ float s_c[TILE_C * DIM];   // 16 KB coord tile
    __shared__ float s_c2[TILE_C];        // |c|^2 per centroid in tile

    const int row  = blockIdx.x * THREADS + threadIdx.x;
    const int rowc = row < n_rows ? row : (n_rows - 1);

    // Latent row in registers (plain float4 loads, unpacked to scalars).
    float xr[DIM];
    {
        const float4* xp = reinterpret_cast<const float4*>(latent + (size_t)rowc * DIM);
        #pragma unroll
        for (int i = 0; i < DIM / 4; i++) {
            float4 v = xp[i];
            xr[4 * i + 0] = v.x;
            xr[4 * i + 1] = v.y;
            xr[4 * i + 2] = v.z;
            xr[4 * i + 3] = v.w;
        }
    }

    float best    = 3.402823466e38f;
    int   bestIdx = 0;

    for (int t0 = 0; t0 < n_cent; t0 += TILE_C) {
        __syncthreads();   // protect previous tile reads before overwrite

        // Cooperative tile load: 32 rows * 128 floats = 1024 float4.
        {
            const float4* gsrc = reinterpret_cast<const float4*>(coords + (size_t)t0 * DIM);
            float4*       sdst = reinterpret_cast<float4*>(s_c);
            #pragma unroll
            for (int k = 0; k < (TILE_C * DIM / 4) / THREADS; k++)
                sdst[threadIdx.x + k * THREADS] = gsrc[threadIdx.x + k * THREADS];
        }
        __syncthreads();

        // |c|^2 per tile row: serial sums by the first TILE_C threads.
        if (threadIdx.x < TILE_C) {
            const float* cp = s_c + threadIdx.x * DIM;
            float s = 0.0f;
            #pragma unroll 8
            for (int i = 0; i < DIM; i++) s = fmaf(cp[i], cp[i], s);
            s_c2[threadIdx.x] = s;
        }
        __syncthreads();

        // Score all centroids in tile (4 independent fmaf chains).
        for (int c = 0; c < TILE_C; c++) {
            const float* cp = s_c + c * DIM;
            float a0 = 0.0f, a1 = 0.0f, a2 = 0.0f, a3 = 0.0f;
            #pragma unroll
            for (int i = 0; i < DIM; i += 4) {
                a0 = fmaf(xr[i + 0], cp[i + 0], a0);
                a1 = fmaf(xr[i + 1], cp[i + 1], a1);
                a2 = fmaf(xr[i + 2], cp[i + 2], a2);
                a3 = fmaf(xr[i + 3], cp[i + 3], a3);
            }
            float dot   = (a0 + a1) + (a2 + a3);
            float score = fmaf(-2.0f, dot, s_c2[c]);
            if (score < best) { best = score; bestIdx = t0 + c; }
        }
    }

    if (row < n_rows) out[row] = (float)bestIdx;   // indices as float32
}

extern "C" void kernel_launch(void* const* d_in, const int* in_sizes, int n_in,
                              void* d_out, int out_size)
{
    // Inputs by size: latent (131072x128) larger than coords (2048x128).
    int i_lat = 0, i_crd = 1;
    if (n_in >= 2 && in_sizes[1] > in_sizes[0]) { i_lat = 1; i_crd = 0; }

    const float* latent = (const float*)d_in[i_lat];
    const float* coords = (const float*)d_in[i_crd];

    int n_rows_a = out_size;                  // output element count
    int n_rows_b = in_sizes[i_lat] / DIM;     // latent row count
    int n_rows = n_rows_a < n_rows_b ? n_rows_a : n_rows_b;
    int n_cent = in_sizes[i_crd] / DIM;       // 2048
    float* out = (float*)d_out;

    dim3 grid((n_rows + THREADS - 1) / THREADS);
    centroids_argmin_kernel<<<grid, THREADS>>>(latent, coords, out, n_rows, n_cent);
}

// round 7
// speedup vs baseline: 1.7224x; 1.7224x over previous
#include <cuda_runtime.h>
#include <cstdint>

// Centroids: out[n] = argmin_c ( |c|^2 - 2 * latent[n].coords[c] )
// Register-blocked fp32 GEMM-argmin:
//   CTA tile: 128 latent rows x 64 centroids, K=128 fully resident.
//   Thread micro-tile: 4 rows x 8 centroids, packed f32x2 FMA accumulators
//   (even/odd k partial sums), LDS.128 staging, padded smem strides.
// Output: float32 indices (established in R6).

#define DIM       128
#define CTA_M     128
#define CTA_N     64
#define THREADS   256
#define LS_STRIDE 132   // 128 + 4 pad (interleaved rows -> 4-bank steps)
#define CS_STRIDE 132

__device__ float g_c2[4096];   // |c|^2 per centroid (scratch, precomputed)

__device__ __forceinline__ unsigned long long ffma2(unsigned long long a,
                                                    unsigned long long b,
                                                    unsigned long long c) {
    unsigned long long d;
    asm("fma.rn.f32x2 %0, %1, %2, %3;" : "=l"(d) : "l"(a), "l"(b), "l"(c));
    return d;
}

__device__ __forceinline__ float2 unpack_f32x2(unsigned long long v) {
    float2 f;
    asm("mov.b64 {%0, %1}, %2;" : "=f"(f.x), "=f"(f.y) : "l"(v));
    return f;
}

// ---- pass 1: |c|^2, one warp per centroid ----
__global__ void c2_kernel(const float* __restrict__ coords, int n_cent) {
    int c    = blockIdx.x * 8 + (threadIdx.x >> 5);
    int lane = threadIdx.x & 31;
    if (c >= n_cent) return;
    const float4* p = reinterpret_cast<const float4*>(coords + (size_t)c * DIM);
    float4 v = p[lane];                       // 32 lanes x 4 = 128 dims
    float s = v.x * v.x + v.y * v.y + v.z * v.z + v.w * v.w;
    #pragma unroll
    for (int off = 16; off > 0; off >>= 1)
        s += __shfl_xor_sync(0xffffffffu, s, off);
    if (lane == 0) g_c2[c] = s;
}

// ---- pass 2: blocked GEMM + running argmin ----
__global__ void __launch_bounds__(THREADS, 1)
centroids_argmin_kernel(const float* __restrict__ latent,
                        const float* __restrict__ coords,
                        float* __restrict__ out,
                        int n_rows, int n_cent)
{
    extern __shared__ float sm[];
    float* Ls  = sm;                          // [128][LS_STRIDE]
    float* Cs  = sm + CTA_M * LS_STRIDE;      // [64][CS_STRIDE]
    float* red = Cs + CTA_N * CS_STRIDE;      // 512 floats (c2 cache + reduce)

    const int tid = threadIdx.x;
    const int tc  = tid & 7;    // centroid group 0..7
    const int mg  = tid >> 3;   // row group 0..31
    const int rowBase = blockIdx.x * CTA_M;

    // Load latent tile [128 x 128] once (row r -> Ls[r][k], padded stride).
    {
        const float4* g = reinterpret_cast<const float4*>(latent);
        #pragma unroll
        for (int t = tid; t < CTA_M * (DIM / 4); t += THREADS) {
            int r  = t >> 5;          // 0..127
            int kq = t & 31;          // 0..31 (float4 index)
            int gr = rowBase + r;
            if (gr >= n_rows) gr = n_rows - 1;
            float4 v = g[(size_t)gr * (DIM / 4) + kq];
            *reinterpret_cast<float4*>(Ls + r * LS_STRIDE + kq * 4) = v;
        }
    }

    float best[4];
    int   bidx[4];
    #pragma unroll
    for (int j = 0; j < 4; j++) { best[j] = 3.402823466e38f; bidx[j] = 0; }

    for (int nb = 0; nb < n_cent; nb += CTA_N) {
        __syncthreads();   // prev-tile reads done (also fences Ls on iter 0... see below)

        // Load coord tile [64 x 128] + c2 slice.
        {
            const float4* g = reinterpret_cast<const float4*>(coords + (size_t)nb * DIM);
            #pragma unroll
            for (int t = tid; t < CTA_N * (DIM / 4); t += THREADS) {
                int r  = t >> 5;
                int kq = t & 31;
                *reinterpret_cast<float4*>(Cs + r * CS_STRIDE + kq * 4) = g[r * (DIM / 4) + kq];
            }
            if (tid < CTA_N) red[tid] = g_c2[nb + tid];
        }
        __syncthreads();

        // 4x8 micro-tile accumulate over K=128 as 32 k-quads.
        unsigned long long acc[4][8];
        #pragma unroll
        for (int j = 0; j < 4; j++)
            #pragma unroll
            for (int i = 0; i < 8; i++) acc[j][i] = 0ull;

        for (int kq = 0; kq < 32; kq++) {
            ulonglong2 a[4], b[8];
            #pragma unroll
            for (int j = 0; j < 4; j++)
                a[j] = *reinterpret_cast<const ulonglong2*>(
                           Ls + (mg + j * 32) * LS_STRIDE + kq * 4);
            #pragma unroll
            for (int i = 0; i < 8; i++)
                b[i] = *reinterpret_cast<const ulonglong2*>(
                           Cs + (i * 8 + tc) * CS_STRIDE + kq * 4);
            #pragma unroll
            for (int j = 0; j < 4; j++)
                #pragma unroll
                for (int i = 0; i < 8; i++) {
                    acc[j][i] = ffma2(a[j].x, b[i].x, acc[j][i]);
                    acc[j][i] = ffma2(a[j].y, b[i].y, acc[j][i]);
                }
        }

        // Fold accumulators, update running argmin.
        #pragma unroll
        for (int j = 0; j < 4; j++)
            #pragma unroll
            for (int i = 0; i < 8; i++) {
                float2 f = unpack_f32x2(acc[j][i]);
                float dot = f.x + f.y;
                int   n   = nb + i * 8 + tc;
                float score = fmaf(-2.0f, dot, red[i * 8 + tc]);
                if (score < best[j]) { best[j] = score; bidx[j] = n; }
            }
    }

    // Reduce across the 8 tc-threads that share each row.
    #pragma unroll
    for (int j = 0; j < 4; j++) {
        __syncthreads();
        red[tid * 2 + 0] = best[j];
        red[tid * 2 + 1] = __int_as_float(bidx[j]);
        __syncthreads();
        if (tid < 32) {
            float bs = 3.402823466e38f;
            int   bi = 0x7fffffff;
            #pragma unroll
            for (int t = 0; t < 8; t++) {
                float s  = red[(tid * 8 + t) * 2 + 0];
                int   ix = __float_as_int(red[(tid * 8 + t) * 2 + 1]);
                if (s < bs || (s == bs && ix < bi)) { bs = s; bi = ix; }
            }
            int row = rowBase + tid + j * 32;
            if (row < n_rows) out[row] = (float)bi;
        }
    }
}

extern "C" void kernel_launch(void* const* d_in, const int* in_sizes, int n_in,
                              void* d_out, int out_size)
{
    // Inputs by size: latent (131072x128) larger than coords (2048x128).
    int i_lat = 0, i_crd = 1;
    if (n_in >= 2 && in_sizes[1] > in_sizes[0]) { i_lat = 1; i_crd = 0; }

    const float* latent = (const float*)d_in[i_lat];
    const float* coords = (const float*)d_in[i_crd];

    int n_rows_a = out_size;
    int n_rows_b = in_sizes[i_lat] / DIM;
    int n_rows = n_rows_a < n_rows_b ? n_rows_a : n_rows_b;
    int n_cent = in_sizes[i_crd] / DIM;       // 2048 (multiple of 64)
    float* out = (float*)d_out;

    static bool attr_set = false;
    if (!attr_set) {
        cudaFuncSetAttribute(centroids_argmin_kernel,
                             cudaFuncAttributeMaxDynamicSharedMemorySize,
                             (CTA_M * LS_STRIDE + CTA_N * CS_STRIDE + 512) * 4);
        attr_set = true;
    }

    c2_kernel<<<(n_cent + 7) / 8, 256>>>(coords, n_cent);

    size_t smem = (CTA_M * LS_STRIDE + CTA_N * CS_STRIDE + 512) * sizeof(float);
    dim3 grid((n_rows + CTA_M - 1) / CTA_M);
    centroids_argmin_kernel<<<grid, THREADS, smem>>>(latent, coords, out,
                                                     n_rows, n_cent);
}